// round 17
// baseline (speedup 1.0000x reference)
#include <cuda_runtime.h>
#include <cuda_fp16.h>
#include <cstdint>

#define NF 32
#define DIM 64
#define NPAIR 496
#define BATCH 2048
#define TILE_H 64                     // A rows per half-CTA
#define LDSTR 72                      // fp16 elems per smem row (64 + 8 pad)

// smem: half H at H*18432: A [0,9216), W [9216,18432). Bounce: per-warp 16 rows x 64B fp16.
#define HALF_BYTES 18432
#define SM_WOFF 9216
#define SM_BNC 36864
#define BNC_WARP 1024                 // 16 * 16 words * 4
#define SM_TOTAL (SM_BNC + 8 * BNC_WARP)   // 45056

#define FE4 (BATCH * NF * DIM / 4)    // 1048576 float4 in fe

// ---- global fp16 scratch (pre-converted) ----
__device__ __align__(16) __half g_feF[BATCH * NF * DIM];
__device__ __align__(16) __half g_WF[NPAIR * DIM * DIM];

__device__ __forceinline__ uint32_t s2u(const void* p) {
    uint32_t a;
    asm("{ .reg .u64 t; cvta.to.shared.u64 t, %1; cvt.u32.u64 %0, t; }" : "=r"(a) : "l"(p));
    return a;
}
__device__ __forceinline__ void cpasync16(uint32_t s, const void* g) {
    asm volatile("{ .reg .u64 gp; cvta.to.global.u64 gp, %1; "
                 "cp.async.ca.shared.global [%0], [gp], 16; }"
                 :: "r"(s), "l"(g) : "memory");
}
__device__ __forceinline__ void ldsm_x4(uint32_t* r, uint32_t a) {
    asm volatile("ldmatrix.sync.aligned.m8n8.x4.shared.b16 {%0,%1,%2,%3}, [%4];"
                 : "=r"(r[0]), "=r"(r[1]), "=r"(r[2]), "=r"(r[3]) : "r"(a));
}
__device__ __forceinline__ void ldsm_x4t(uint32_t* r, uint32_t a) {
    asm volatile("ldmatrix.sync.aligned.m8n8.x4.trans.shared.b16 {%0,%1,%2,%3}, [%4];"
                 : "=r"(r[0]), "=r"(r[1]), "=r"(r[2]), "=r"(r[3]) : "r"(a));
}
__device__ __forceinline__ void mma_f16(float* d, const uint32_t* a, const uint32_t* b) {
    asm volatile("mma.sync.aligned.m16n8k16.row.col.f32.f16.f16.f32 "
                 "{%0,%1,%2,%3}, {%4,%5,%6,%7}, {%8,%9}, {%0,%1,%2,%3};"
                 : "+f"(d[0]), "+f"(d[1]), "+f"(d[2]), "+f"(d[3])
                 : "r"(a[0]), "r"(a[1]), "r"(a[2]), "r"(a[3]), "r"(b[0]), "r"(b[1]));
}

// ---- fused prep kernel: fp32 -> fp16 ----
__global__ __launch_bounds__(256) void cvt_all_kernel(
    const float* __restrict__ fe, const float* __restrict__ W) {
    int idx = blockIdx.x * 256 + threadIdx.x;
    float4 v;
    __half2* dst;
    if (idx < FE4) {
        v = reinterpret_cast<const float4*>(fe)[idx];
        dst = reinterpret_cast<__half2*>(g_feF) + idx * 2;
    } else {
        v = reinterpret_cast<const float4*>(W)[idx - FE4];
        dst = reinterpret_cast<__half2*>(g_WF) + (idx - FE4) * 2;
    }
    dst[0] = __floats2half2_rn(v.x, v.y);
    dst[1] = __floats2half2_rn(v.z, v.w);
}

// swizzled word index into the per-warp bounce: row lrow (0..15), half2-group g (0..3)
__device__ __forceinline__ int bnc_word(int lrow, int g) {
    return lrow * 16 + ((((g + (lrow >> 2)) & 3) ^ (lrow & 3)) << 2);
}

// out[b, p, e] = (sum_d fe[b, i(p), d] * W[p, d, e]) * fe[b, j(p), e]
__global__ __launch_bounds__(256, 3) void bilinear_mma_kernel(
    const float* __restrict__ fe,   // fp32, for v_j epilogue
    float* __restrict__ out)
{
    extern __shared__ char smem[];
    const uint32_t base = s2u(smem);
    const int tid   = threadIdx.x;      // 0..255
    const int H     = tid >> 7;         // half 0/1
    const int htid  = tid & 127;
    const int hwid  = htid >> 5;        // 0..3 within half
    const int wid   = tid >> 5;         // 0..7 global
    const int lid   = tid & 31;
    const int p     = blockIdx.y;       // pair 0..495
    const int btile = blockIdx.x * 2 + H;   // 64-row tile index, 0..31

    // decode (i, j) from triu_indices(NF, k=1)
    int i = 0, rem = p;
    while (rem >= NF - 1 - i) { rem -= NF - 1 - i; ++i; }
    const int j = i + 1 + rem;

    const uint32_t hbase = base + (uint32_t)(H * HALF_BYTES);

    // ---- async loads (per half; fully independent) ----
    // W: 64 rows x 64 fp16 = 512 x 16B chunks, 4/half-thread
    {
        #pragma unroll
        for (int q = 0; q < 4; ++q) {
            int chunk = htid + 128 * q;                   // 0..511
            int row = chunk >> 3, c = chunk & 7;
            const size_t gb = (size_t)p * DIM * DIM + row * DIM + c * 8;
            cpasync16(hbase + SM_WOFF + (uint32_t)(row * (LDSTR * 2) + c * 16), g_WF + gb);
        }
    }
    // A: 64 rows x 64 fp16 = 512 chunks, 4/half-thread
    {
        #pragma unroll
        for (int q = 0; q < 4; ++q) {
            int chunk = htid + 128 * q;                   // 0..511
            int row = chunk >> 3, c = chunk & 7;
            const size_t gb = ((size_t)(btile * TILE_H + row) * NF + i) * DIM + c * 8;
            cpasync16(hbase + (uint32_t)(row * (LDSTR * 2) + c * 16), g_feF + gb);
        }
    }
    asm volatile("cp.async.commit_group;" ::: "memory");
    asm volatile("cp.async.wait_group 0;" ::: "memory");
    // half-scoped barrier: only this half's 128 threads
    asm volatile("bar.sync %0, 128;" :: "r"(1 + H) : "memory");

    // ---- warp tile: 32 (m) x 32 (n); 2x2 warp grid per half ----
    const int MR = (hwid & 1) * 32;
    const int NC = (hwid >> 1) * 32;
    const int lr = lid & 15, lc = lid >> 4;

    const uint32_t aA0 = hbase + (uint32_t)(MR + lr) * (LDSTR * 2) + lc * 16;
    const uint32_t aA1 = aA0 + 16 * (LDSTR * 2);
    const uint32_t aW  = hbase + SM_WOFF + (uint32_t)lr * (LDSTR * 2) + NC * 2 + lc * 16;

    float acc[2][4][4] = {};

    #pragma unroll
    for (int ks = 0; ks < 4; ++ks) {
        const uint32_t kA = (uint32_t)(ks * 32);               // +16 k-cols (bytes)
        const uint32_t kB = (uint32_t)(ks * 16 * (LDSTR * 2)); // +16 k-rows (bytes)

        uint32_t af[2][4], wf[8];
        ldsm_x4(af[0], aA0 + kA);
        ldsm_x4(af[1], aA1 + kA);
        ldsm_x4t(wf,     aW + kB);
        ldsm_x4t(wf + 4, aW + kB + 32);

        #pragma unroll
        for (int mi = 0; mi < 2; ++mi)
            #pragma unroll
            for (int ni = 0; ni < 4; ++ni)
                mma_f16(acc[mi][ni], af[mi], &wf[ni * 2]);
    }

    // ---- epilogue: per-warp fp16 bounce, XOR-swizzled, warp-local sync only ----
    uint32_t* b32 = reinterpret_cast<uint32_t*>(smem + SM_BNC + wid * BNC_WARP);
    const int r  = lid >> 2;
    const int c3 = lid & 3;

    #pragma unroll
    for (int mi = 0; mi < 2; ++mi) {
        // write: pack float2 -> half2, swizzled STS.32 (conflict-free)
        #pragma unroll
        for (int h = 0; h < 2; ++h) {
            const int lrow = h * 8 + r;                        // 0..15
            #pragma unroll
            for (int ni = 0; ni < 4; ++ni) {
                __half2 hv = __floats2half2_rn(acc[mi][ni][h * 2 + 0],
                                               acc[mi][ni][h * 2 + 1]);
                b32[bnc_word(lrow, ni) + c3] = *reinterpret_cast<uint32_t*>(&hv);
            }
        }
        __syncwarp();

        // read: LDS.128 (4 half2 = 8 cols), vj fp32, STG.128 x2
        #pragma unroll
        for (int rr = 0; rr < 2; ++rr) {
            const int lrow = rr * 8 + r;                       // 0..15
            uint4 raw = *reinterpret_cast<const uint4*>(&b32[bnc_word(lrow, c3)]);

            const int b = btile * TILE_H + MR + mi * 16 + lrow;
            const int col = NC + c3 * 8;
            const float* vjr = fe + ((size_t)b * NF + j) * DIM + col;
            float4 vj0 = *reinterpret_cast<const float4*>(vjr);
            float4 vj1 = *reinterpret_cast<const float4*>(vjr + 4);

            float2 f0 = __half22float2(*reinterpret_cast<__half2*>(&raw.x));
            float2 f1 = __half22float2(*reinterpret_cast<__half2*>(&raw.y));
            float2 f2 = __half22float2(*reinterpret_cast<__half2*>(&raw.z));
            float2 f3 = __half22float2(*reinterpret_cast<__half2*>(&raw.w));

            float4 o0 = make_float4(f0.x * vj0.x, f0.y * vj0.y, f1.x * vj0.z, f1.y * vj0.w);
            float4 o1 = make_float4(f2.x * vj1.x, f2.y * vj1.y, f3.x * vj1.z, f3.y * vj1.w);

            float* orow = out + ((size_t)b * NPAIR + p) * DIM + col;
            *reinterpret_cast<float4*>(orow)     = o0;
            *reinterpret_cast<float4*>(orow + 4) = o1;
        }
        __syncwarp();
    }
}

extern "C" void kernel_launch(void* const* d_in, const int* in_sizes, int n_in,
                              void* d_out, int out_size) {
    const float* fe = (const float*)d_in[0];   // feature_emb [2048, 32, 64] fp32
    const float* W  = (const float*)d_in[1];   // bilinear_W [496, 64, 64] fp32
    float* out = (float*)d_out;                // [2048, 496, 64] fp32

    const int n4 = FE4 + NPAIR * DIM * DIM / 4;     // 1556480 float4 total
    cvt_all_kernel<<<(n4 + 255) / 256, 256>>>(fe, W);

    cudaFuncSetAttribute(bilinear_mma_kernel,
                         cudaFuncAttributeMaxDynamicSharedMemorySize, SM_TOTAL);
    dim3 grid(BATCH / (2 * TILE_H), NPAIR);    // (16, 496)
    bilinear_mma_kernel<<<grid, 256, SM_TOTAL>>>(fe, out);
}